// round 7
// baseline (speedup 1.0000x reference)
#include <cuda_runtime.h>
#include <cstdint>
#include <cstddef>

#define BB 64
#define SS 2048
#define DIN 512
#define HH 1024
#define SPLITS 8                       // tiles per batch; 512 tiles total
#define NTILES (BB * SPLITS)
#define ROWS_PER_TILE (SS / SPLITS)    // 256
#define NWARP 16
#define RING_DEPTH 3
#define GRID 148                       // == min SM count; all CTAs co-resident

#define NEG_INF __int_as_float(0xff800000)

// ---------------- scratch (no allocations allowed) ----------------
__device__ __align__(16) float g_x[BB * HH];            // inp@W + b
__device__ unsigned char  g_mask[BB * SS];              // canonical mask (1 = masked)
__device__ float          g_score[BB * SS];             // raw scores (-inf where masked)
__device__ __align__(16) float g_acc[NTILES * HH];      // tile partial weighted sums
__device__ float          g_l[NTILES];                  // tile partial sum-of-exp
__device__ unsigned       g_ticket;                     // tile work queue
__device__ unsigned       g_bdone[BB];                  // per-batch tile completion
__device__ unsigned       g_bar;                        // grid barrier counter
__device__ unsigned       g_exit;                       // exit counter (for resets)

// ---------------- helpers ----------------
__device__ __forceinline__ float tanh_fast(float x) {
    float y;
    asm("tanh.approx.f32 %0, %1;" : "=f"(y) : "f"(x));
    return y;
}

__device__ __forceinline__ void issue_row(const float* cb, int k, int n,
                                          unsigned slot_u32, int ln,
                                          const int* s_idx) {
    if (k < n) {
        const float* src = cb + (size_t)s_idx[k] * HH + ln * 4;
        unsigned dst = slot_u32 + ln * 16;
#pragma unroll
        for (int i = 0; i < 8; i++)
            asm volatile("cp.async.cg.shared.global [%0], [%1], 16;"
                         :: "r"(dst + i * 512), "l"(src + i * 128) : "memory");
    }
    asm volatile("cp.async.commit_group;" ::: "memory");
}

// ---------------- the one kernel ----------------
// Phase 0: mask canonicalize (all CTAs) + x = inp@W + b (CTAs 0..127, 8 H-cols each)
// grid barrier
// Phase 1: persistent ticketed tiles: scores + exp-sum + weighted sum + finalize
__global__ __launch_bounds__(512, 1) void mega_kernel(const float* __restrict__ inp,
                                                      const float* __restrict__ Wm,
                                                      const float* __restrict__ bias,
                                                      const void*  __restrict__ mraw,
                                                      const float* __restrict__ ctx,
                                                      const float* __restrict__ v,
                                                      float* __restrict__ out_applied,
                                                      float* __restrict__ out_w) {
    extern __shared__ float dsm[];

    __shared__ int      s_idx[ROWS_PER_TILE];
    __shared__ int      s_wcnt[8];
    __shared__ float    s_l[NWARP];
    __shared__ unsigned s_tile;
    __shared__ int      s_last;

    int t  = threadIdx.x;
    int w  = t >> 5;
    int ln = t & 31;

    // ================= phase 0a: mask canonicalize (all CTAs) ==============
    {
        const unsigned* wds = (const unsigned*)mraw;
        int notInt = 0, notFloat = 0;
        for (int i = t; i < 1024; i += 512) {
            unsigned x = wds[i];
            notInt   |= (x > 1u);
            notFloat |= (x != 0u && x != 0x3F800000u);
        }
        notInt   = __syncthreads_or(notInt);
        notFloat = __syncthreads_or(notFloat);
        int mode = notInt ? (notFloat ? 2 : 1) : 0;  // 0:int32 1:float32 2:bytes
        for (int i = blockIdx.x * 512 + t; i < BB * SS; i += GRID * 512) {
            unsigned char mv;
            if (mode == 0)      mv = (((const int*)mraw)[i] != 0);
            else if (mode == 1) mv = (((const float*)mraw)[i] != 0.0f);
            else                mv = (((const unsigned char*)mraw)[i] != 0);
            g_mask[i] = mv;
        }
    }

    // ================= phase 0b: x-GEMM (CTAs 0..127) ======================
    if (blockIdx.x < 128) {
        float4* inp4 = (float4*)dsm;               // [64][129] float4 (padded)
        float*  Wt   = dsm + 33024;                // [8][516] floats (padded)
        int h0 = blockIdx.x * 8;

        for (int i = t; i < 8192; i += 512) {      // inp: 64x512 = 8192 float4
            int b = i >> 7, kq = i & 127;
            inp4[b * 129 + kq] = ((const float4*)inp)[i];
        }
        for (int i = t; i < 1024; i += 512) {      // W slab, transposed
            int k = i >> 1, jj = (i & 1) * 4;
            float4 wv = *(const float4*)&Wm[(size_t)k * HH + h0 + jj];
            Wt[(jj + 0) * 516 + k] = wv.x;
            Wt[(jj + 1) * 516 + k] = wv.y;
            Wt[(jj + 2) * 516 + k] = wv.z;
            Wt[(jj + 3) * 516 + k] = wv.w;
        }
        __syncthreads();

        int b = t >> 3, j = t & 7;
        const float4* ivp = inp4 + b * 129;
        const float4* wtp = (const float4*)&Wt[j * 516];
        float a0 = 0.f, a1 = 0.f, a2 = 0.f, a3 = 0.f;
#pragma unroll 8
        for (int kq = 0; kq < 128; kq++) {
            float4 iv = ivp[kq];
            float4 wv = wtp[kq];
            a0 = fmaf(iv.x, wv.x, a0);
            a1 = fmaf(iv.y, wv.y, a1);
            a2 = fmaf(iv.z, wv.z, a2);
            a3 = fmaf(iv.w, wv.w, a3);
        }
        g_x[b * HH + h0 + j] = ((a0 + a1) + (a2 + a3)) + bias[h0 + j];
        __syncthreads();                           // done with GEMM smem
    }

    // ================= grid barrier ========================================
    if (t == 0) {
        __threadfence();
        atomicAdd(&g_bar, 1u);
        unsigned x;
        do {
            asm volatile("ld.acquire.gpu.global.b32 %0, [%1];"
                         : "=r"(x) : "l"(&g_bar) : "memory");
        } while (x < GRID);
    }
    __syncthreads();

    // ================= phase 1: persistent tiles ===========================
    float* xs   = dsm;                 // HH floats
    float* ring = dsm + HH;            // NWARP * RING_DEPTH * HH floats

    float4 vv[8];
    const float4* vr = (const float4*)v;
#pragma unroll
    for (int j = 0; j < 8; j++) vv[j] = __ldg(&vr[j * 32 + ln]);

    float* myring = ring + w * (RING_DEPTH * HH);
    unsigned ring_u32 = (unsigned)__cvta_generic_to_shared(myring);

    for (;;) {
        if (t == 0) s_tile = atomicAdd(&g_ticket, 1u);
        __syncthreads();               // also orders prior tile's smem reuse
        unsigned tile = s_tile;
        if (tile >= NTILES) break;

        int b  = tile >> 3;            // SPLITS = 8
        int sp = tile & (SPLITS - 1);
        int rowbase = b * SS + sp * ROWS_PER_TILE;

        xs[t]       = g_x[b * HH + t];
        xs[t + 512] = g_x[b * HH + 512 + t];

        // ---- compact unmasked row indices (deterministic order) ----
        unsigned char mk = 1;
        if (t < ROWS_PER_TILE) mk = g_mask[rowbase + t];
        unsigned bits = __ballot_sync(0xffffffffu, mk == 0);
        if (t < ROWS_PER_TILE && mk) g_score[rowbase + t] = NEG_INF;
        if (w < 8 && ln == 0) s_wcnt[w] = __popc(bits);
        __syncthreads();
        int n = 0;
#pragma unroll
        for (int i = 0; i < 8; i++) n += s_wcnt[i];
        if (t < ROWS_PER_TILE && !mk) {
            int basew = 0;
#pragma unroll
            for (int i = 0; i < 8; i++) if (i < w) basew += s_wcnt[i];
            s_idx[basew + __popc(bits & ((1u << ln) - 1u))] = t;
        }
        __syncthreads();

        // ---- per-warp row loop over compacted list ----
        float4 acc[8];
#pragma unroll
        for (int j = 0; j < 8; j++) acc[j] = make_float4(0.f, 0.f, 0.f, 0.f);
        float l = 0.f;

        const float* cb = ctx + (size_t)rowbase * HH;
        issue_row(cb, w,             n, ring_u32,          ln, s_idx);
        issue_row(cb, w + NWARP,     n, ring_u32 + HH * 4, ln, s_idx);
        issue_row(cb, w + 2 * NWARP, n, ring_u32 + HH * 8, ln, s_idx);
        int slot = 0;
        for (int k = w; k < n; k += NWARP) {
            asm volatile("cp.async.wait_group 2;" ::: "memory");
            const float* sp_ = myring + slot * HH;

            float4 cc[8];
            float part = 0.f;
#pragma unroll
            for (int j = 0; j < 8; j++) {
                cc[j] = *(const float4*)&sp_[j * 128 + ln * 4];
                float4 xj = *(const float4*)&xs[j * 128 + ln * 4];
                float4 vg = vv[j];
                part = fmaf(tanh_fast(xj.x + cc[j].x), vg.x, part);
                part = fmaf(tanh_fast(xj.y + cc[j].y), vg.y, part);
                part = fmaf(tanh_fast(xj.z + cc[j].z), vg.z, part);
                part = fmaf(tanh_fast(xj.w + cc[j].w), vg.w, part);
            }
#pragma unroll
            for (int off = 16; off; off >>= 1)
                part += __shfl_xor_sync(0xffffffffu, part, off);

            if (ln == 0) g_score[rowbase + s_idx[k]] = part;
            float p = __expf(part);    // fixed reference M=0: |score| < 40
            l += p;
#pragma unroll
            for (int j = 0; j < 8; j++) {
                acc[j].x = fmaf(cc[j].x, p, acc[j].x);
                acc[j].y = fmaf(cc[j].y, p, acc[j].y);
                acc[j].z = fmaf(cc[j].z, p, acc[j].z);
                acc[j].w = fmaf(cc[j].w, p, acc[j].w);
            }
            issue_row(cb, k + 3 * NWARP, n, ring_u32 + slot * HH * 4, ln, s_idx);
            slot = (slot == RING_DEPTH - 1) ? 0 : slot + 1;
        }
        asm volatile("cp.async.wait_group 0;" ::: "memory");

        // ---- CTA combine: overlay acc onto ring smem, tree-reduce ----
        if (ln == 0) s_l[w] = l;
        __syncthreads();
        float* sout = ring;
#pragma unroll
        for (int j = 0; j < 8; j++)
            *(float4*)&sout[w * HH + j * 128 + ln * 4] = acc[j];
        __syncthreads();

        float L = 0.f;
#pragma unroll
        for (int i = 0; i < NWARP; i++) L += s_l[i];
        float sum0 = 0.f, sum1 = 0.f;
#pragma unroll
        for (int i = 0; i < NWARP; i++) {
            sum0 += sout[i * HH + t];
            sum1 += sout[i * HH + t + 512];
        }
        g_acc[(size_t)tile * HH + t]       = sum0;
        g_acc[(size_t)tile * HH + t + 512] = sum1;
        if (t == 0) g_l[tile] = L;

        // ---- last tile of this batch? finalize the batch here ----
        __threadfence();
        if (t == 0) {
            unsigned old = atomicAdd(&g_bdone[b], 1u);
            s_last = (old == SPLITS - 1);
        }
        __syncthreads();
        if (s_last) {
            float Lb = 0.f;
#pragma unroll
            for (int i = 0; i < SPLITS; i++) Lb += __ldcg(&g_l[b * SPLITS + i]);
            float invL = 1.0f / Lb;
#pragma unroll
            for (int r = 0; r < 2; r++) {
                int h = t + r * 512;
                float s = 0.f;
#pragma unroll
                for (int i = 0; i < SPLITS; i++)
                    s += __ldcg(&g_acc[(size_t)(b * SPLITS + i) * HH + h]);
                out_applied[b * HH + h] = s * invL;
            }
#pragma unroll
            for (int r = 0; r < 4; r++) {
                int si = t + r * 512;
                float sc = __ldcg(&g_score[b * SS + si]);  // -inf masked -> 0
                out_w[b * SS + si] = __expf(sc) * invL;
            }
        }
    }

    // ================= exit: last CTA resets all persistent state ==========
    __syncthreads();
    if (t == 0) {
        __threadfence();
        unsigned old = atomicAdd(&g_exit, 1u);
        if (old == GRID - 1) {
            g_ticket = 0;
#pragma unroll
            for (int i = 0; i < BB; i++) g_bdone[i] = 0;
            g_bar  = 0;
            g_exit = 0;
        }
    }
}

// ---------------- launch ----------------
extern "C" void kernel_launch(void* const* d_in, const int* in_sizes, int n_in,
                              void* d_out, int out_size) {
    const float* inp  = (const float*)d_in[0];
    // d_in[1] = hidden (unused by the reference computation)
    const float* ctx  = (const float*)d_in[2];
    const void*  mask = d_in[3];
    const float* Wm   = (const float*)d_in[4];
    const float* bias = (const float*)d_in[5];
    const float* v    = (const float*)d_in[6];
    float* out = (float*)d_out;

    const int dyn_smem = (HH + NWARP * RING_DEPTH * HH) * (int)sizeof(float); // 200704
    cudaFuncSetAttribute(mega_kernel,
                         cudaFuncAttributeMaxDynamicSharedMemorySize, dyn_smem);

    mega_kernel<<<GRID, 512, dyn_smem>>>(inp, Wm, bias, mask, ctx, v,
                                         out, out + BB * HH);
}

// round 8
// speedup vs baseline: 1.0004x; 1.0004x over previous
#include <cuda_runtime.h>
#include <cstdint>
#include <cstddef>

#define BB 64
#define SS 2048
#define DIN 512
#define HH 1024
#define SPLITS 8                       // tiles per batch; 512 tiles total
#define NTILES (BB * SPLITS)
#define ROWS_PER_TILE (SS / SPLITS)    // 256
#define NWARP 16
#define RING_DEPTH 3
#define GRID 148                       // == min SM count; all CTAs co-resident

#define NEG_INF __int_as_float(0xff800000)

// ---------------- scratch (no allocations allowed) ----------------
__device__ __align__(16) float g_x[BB * HH];            // inp@W + b
__device__ unsigned char  g_mask[BB * SS];              // canonical mask (1 = masked)
__device__ float          g_score[BB * SS];             // raw scores (-inf where masked)
__device__ __align__(16) float g_acc[NTILES * HH];      // tile partial weighted sums
__device__ float          g_l[NTILES];                  // tile partial sum-of-exp
__device__ unsigned       g_ticket;                     // tile work queue
__device__ unsigned       g_bdone[BB];                  // per-batch tile completion
__device__ unsigned       g_bar;                        // grid barrier counter
__device__ unsigned       g_exit;                       // exit counter (for resets)

// ---------------- helpers ----------------
__device__ __forceinline__ float tanh_fast(float x) {
    float y;
    asm("tanh.approx.f32 %0, %1;" : "=f"(y) : "f"(x));
    return y;
}

__device__ __forceinline__ void issue_row(const float* cb, int k, int n,
                                          unsigned slot_u32, int ln,
                                          const int* s_idx) {
    if (k < n) {
        const float* src = cb + (size_t)s_idx[k] * HH + ln * 4;
        unsigned dst = slot_u32 + ln * 16;
#pragma unroll
        for (int i = 0; i < 8; i++)
            asm volatile("cp.async.cg.shared.global [%0], [%1], 16;"
                         :: "r"(dst + i * 512), "l"(src + i * 128) : "memory");
    }
    asm volatile("cp.async.commit_group;" ::: "memory");
}

// ---------------- the one kernel ----------------
__global__ __launch_bounds__(512, 1) void mega_kernel(const float* __restrict__ inp,
                                                      const float* __restrict__ Wm,
                                                      const float* __restrict__ bias,
                                                      const void*  __restrict__ mraw,
                                                      const float* __restrict__ ctx,
                                                      const float* __restrict__ v,
                                                      float* __restrict__ out_applied,
                                                      float* __restrict__ out_w) {
    extern __shared__ float dsm[];

    __shared__ int      s_idx[ROWS_PER_TILE];
    __shared__ int      s_wcnt[8];
    __shared__ float    s_l[NWARP];
    __shared__ unsigned s_tile;
    __shared__ int      s_last;

    int t  = threadIdx.x;
    int w  = t >> 5;
    int ln = t & 31;

    // ================= phase 0a: mask canonicalize (all CTAs) ==============
    {
        const unsigned* wds = (const unsigned*)mraw;
        int notInt = 0, notFloat = 0;
        for (int i = t; i < 1024; i += 512) {
            unsigned x = wds[i];
            notInt   |= (x > 1u);
            notFloat |= (x != 0u && x != 0x3F800000u);
        }
        notInt   = __syncthreads_or(notInt);
        notFloat = __syncthreads_or(notFloat);
        int mode = notInt ? (notFloat ? 2 : 1) : 0;  // 0:int32 1:float32 2:bytes
        for (int i = blockIdx.x * 512 + t; i < BB * SS; i += GRID * 512) {
            unsigned char mv;
            if (mode == 0)      mv = (((const int*)mraw)[i] != 0);
            else if (mode == 1) mv = (((const float*)mraw)[i] != 0.0f);
            else                mv = (((const unsigned char*)mraw)[i] != 0);
            g_mask[i] = mv;
        }
    }

    // ================= phase 0b: x-GEMM (CTAs 0..127) ======================
    if (blockIdx.x < 128) {
        float4* inp4 = (float4*)dsm;               // [64][129] float4 (padded)
        float*  Wt   = dsm + 33024;                // [8][516] floats (padded)
        int h0 = blockIdx.x * 8;

        for (int i = t; i < 8192; i += 512) {      // inp: 64x512 = 8192 float4
            int b = i >> 7, kq = i & 127;
            inp4[b * 129 + kq] = ((const float4*)inp)[i];
        }
        for (int i = t; i < 1024; i += 512) {      // W slab, transposed
            int k = i >> 1, jj = (i & 1) * 4;
            float4 wv = *(const float4*)&Wm[(size_t)k * HH + h0 + jj];
            Wt[(jj + 0) * 516 + k] = wv.x;
            Wt[(jj + 1) * 516 + k] = wv.y;
            Wt[(jj + 2) * 516 + k] = wv.z;
            Wt[(jj + 3) * 516 + k] = wv.w;
        }
        __syncthreads();

        int b = t >> 3, j = t & 7;
        const float4* ivp = inp4 + b * 129;
        const float4* wtp = (const float4*)&Wt[j * 516];
        float a0 = 0.f, a1 = 0.f, a2 = 0.f, a3 = 0.f;
#pragma unroll 8
        for (int kq = 0; kq < 128; kq++) {
            float4 iv = ivp[kq];
            float4 wv = wtp[kq];
            a0 = fmaf(iv.x, wv.x, a0);
            a1 = fmaf(iv.y, wv.y, a1);
            a2 = fmaf(iv.z, wv.z, a2);
            a3 = fmaf(iv.w, wv.w, a3);
        }
        g_x[b * HH + h0 + j] = ((a0 + a1) + (a2 + a3)) + bias[h0 + j];
        __syncthreads();                           // done with GEMM smem
    }

    // ================= grid barrier ========================================
    if (t == 0) {
        __threadfence();
        atomicAdd(&g_bar, 1u);
        unsigned x;
        do {
            asm volatile("ld.acquire.gpu.global.b32 %0, [%1];"
                         : "=r"(x) : "l"(&g_bar) : "memory");
        } while (x < GRID);
    }
    __syncthreads();

    // ================= phase 1: persistent tiles ===========================
    float* xs   = dsm;                 // HH floats
    float* ring = dsm + HH;            // NWARP * RING_DEPTH * HH floats

    float4 vv[8];
    const float4* vr = (const float4*)v;
#pragma unroll
    for (int j = 0; j < 8; j++) vv[j] = __ldg(&vr[j * 32 + ln]);

    float* myring = ring + w * (RING_DEPTH * HH);
    unsigned ring_u32 = (unsigned)__cvta_generic_to_shared(myring);

    for (;;) {
        if (t == 0) s_tile = atomicAdd(&g_ticket, 1u);
        __syncthreads();               // also orders prior tile's smem reuse
        unsigned tile = s_tile;
        if (tile >= NTILES) break;

        int b  = tile >> 3;            // SPLITS = 8
        int sp = tile & (SPLITS - 1);
        int rowbase = b * SS + sp * ROWS_PER_TILE;

        xs[t]       = g_x[b * HH + t];
        xs[t + 512] = g_x[b * HH + 512 + t];

        // ---- compact unmasked row indices (deterministic order) ----
        unsigned char mk = 1;
        if (t < ROWS_PER_TILE) mk = g_mask[rowbase + t];
        unsigned bits = __ballot_sync(0xffffffffu, mk == 0);
        if (t < ROWS_PER_TILE && mk) g_score[rowbase + t] = NEG_INF;
        if (w < 8 && ln == 0) s_wcnt[w] = __popc(bits);
        __syncthreads();
        int n = 0;
#pragma unroll
        for (int i = 0; i < 8; i++) n += s_wcnt[i];
        if (t < ROWS_PER_TILE && !mk) {
            int basew = 0;
#pragma unroll
            for (int i = 0; i < 8; i++) if (i < w) basew += s_wcnt[i];
            s_idx[basew + __popc(bits & ((1u << ln) - 1u))] = t;
        }
        __syncthreads();

        // ---- per-warp row loop over compacted list (NO row regs: no spill) -
        float4 acc[8];
#pragma unroll
        for (int j = 0; j < 8; j++) acc[j] = make_float4(0.f, 0.f, 0.f, 0.f);
        float l = 0.f;

        const float* cb = ctx + (size_t)rowbase * HH;
        issue_row(cb, w,             n, ring_u32,          ln, s_idx);
        issue_row(cb, w + NWARP,     n, ring_u32 + HH * 4, ln, s_idx);
        issue_row(cb, w + 2 * NWARP, n, ring_u32 + HH * 8, ln, s_idx);
        int slot = 0;
        for (int k = w; k < n; k += NWARP) {
            asm volatile("cp.async.wait_group 2;" ::: "memory");
            const float* sp_ = myring + slot * HH;

            float part = 0.f;
#pragma unroll
            for (int j = 0; j < 8; j++) {
                float4 c  = *(const float4*)&sp_[j * 128 + ln * 4];
                float4 xj = *(const float4*)&xs[j * 128 + ln * 4];
                float4 vg = vv[j];
                part = fmaf(tanh_fast(xj.x + c.x), vg.x, part);
                part = fmaf(tanh_fast(xj.y + c.y), vg.y, part);
                part = fmaf(tanh_fast(xj.z + c.z), vg.z, part);
                part = fmaf(tanh_fast(xj.w + c.w), vg.w, part);
            }
#pragma unroll
            for (int off = 16; off; off >>= 1)
                part += __shfl_xor_sync(0xffffffffu, part, off);

            if (ln == 0) g_score[rowbase + s_idx[k]] = part;
            float p = __expf(part);    // fixed reference M=0: |score| < 40
            l += p;
#pragma unroll
            for (int j = 0; j < 8; j++) {          // re-read row (LDS, no spill)
                float4 c = *(const float4*)&sp_[j * 128 + ln * 4];
                acc[j].x = fmaf(c.x, p, acc[j].x);
                acc[j].y = fmaf(c.y, p, acc[j].y);
                acc[j].z = fmaf(c.z, p, acc[j].z);
                acc[j].w = fmaf(c.w, p, acc[j].w);
            }
            issue_row(cb, k + 3 * NWARP, n, ring_u32 + slot * HH * 4, ln, s_idx);
            slot = (slot == RING_DEPTH - 1) ? 0 : slot + 1;
        }
        asm volatile("cp.async.wait_group 0;" ::: "memory");

        // ---- CTA combine: overlay acc onto ring smem, tree-reduce ----
        if (ln == 0) s_l[w] = l;
        __syncthreads();
        float* sout = ring;
#pragma unroll
        for (int j = 0; j < 8; j++)
            *(float4*)&sout[w * HH + j * 128 + ln * 4] = acc[j];
        __syncthreads();

        float L = 0.f;
#pragma unroll
        for (int i = 0; i < NWARP; i++) L += s_l[i];
        float sum0 = 0.f, sum1 = 0.f;
#pragma unroll
        for (int i = 0; i < NWARP; i++) {
            sum0 += sout[i * HH + t];
            sum1 += sout[i * HH + t + 512];
        }
        g_acc[(size_t)tile * HH + t]       = sum0;
        g_acc[(size_t)tile * HH + t + 512] = sum1;
        if (t == 0) g_l[tile] = L;

        // ---- last tile of this batch? finalize the batch here ----
        __threadfence();
        if (t == 0) {
            unsigned old = atomicAdd(&g_bdone[b], 1u);
            s_last = (old == SPLITS - 1);
        }
        __syncthreads();
        if (s_last) {
            float Lb = 0.f;
#pragma unroll
            for (int i = 0; i < SPLITS; i++) Lb += __ldcg(&g_l[b * SPLITS + i]);
            float invL = 1.0f / Lb;
#pragma unroll
            for (int r = 0; r < 2; r++) {
                int h = t + r * 512;
                float s = 0.f;
#pragma unroll
                for (int i = 0; i < SPLITS; i++)
                    s += __ldcg(&g_acc[(size_t)(b * SPLITS + i) * HH + h]);
                out_applied[b * HH + h] = s * invL;
            }
#pragma unroll
            for (int r = 0; r < 4; r++) {
                int si = t + r * 512;
                float sc = __ldcg(&g_score[b * SS + si]);  // -inf masked -> 0
                out_w[b * SS + si] = __expf(sc) * invL;
            }
        }
    }

    // ================= exit: last CTA resets all persistent state ==========
    __syncthreads();
    if (t == 0) {
        __threadfence();
        unsigned old = atomicAdd(&g_exit, 1u);
        if (old == GRID - 1) {
            g_ticket = 0;
#pragma unroll
            for (int i = 0; i < BB; i++) g_bdone[i] = 0;
            g_bar  = 0;
            g_exit = 0;
        }
    }
}

// ---------------- launch ----------------
extern "C" void kernel_launch(void* const* d_in, const int* in_sizes, int n_in,
                              void* d_out, int out_size) {
    const float* inp  = (const float*)d_in[0];
    // d_in[1] = hidden (unused by the reference computation)
    const float* ctx  = (const float*)d_in[2];
    const void*  mask = d_in[3];
    const float* Wm   = (const float*)d_in[4];
    const float* bias = (const float*)d_in[5];
    const float* v    = (const float*)d_in[6];
    float* out = (float*)d_out;

    const int dyn_smem = (HH + NWARP * RING_DEPTH * HH) * (int)sizeof(float); // 200704
    cudaFuncSetAttribute(mega_kernel,
                         cudaFuncAttributeMaxDynamicSharedMemorySize, dyn_smem);

    mega_kernel<<<GRID, 512, dyn_smem>>>(inp, Wm, bias, mask, ctx, v,
                                         out, out + BB * HH);
}